// round 1
// baseline (speedup 1.0000x reference)
#include <cuda_runtime.h>
#include <math.h>

#define SIZE_IN  4096
#define SIZE_OUT 4096
#define BATCH    4096
#define NW (SIZE_IN * SIZE_OUT)

// Scratch: precomputed softplus(w_sigma) (64 MB) + KL scalar accumulators.
__device__ float  g_sp[NW];
__device__ double g_sums[3];   // [0]=sum log(sp), [1]=sum sp, [2]=sum |w_mu|

__device__ __forceinline__ float softplusf(float x) {
    // stable softplus; inputs here are <= ~0 or small, but keep the guard
    return x > 20.0f ? x : log1pf(expf(x));
}

__global__ void init_kernel() {
    if (threadIdx.x < 3) g_sums[threadIdx.x] = 0.0;
}

// Precompute softplus(w_sigma) into g_sp and reduce KL scalars.
__global__ void prep_kernel(const float* __restrict__ w_sigma,
                            const float* __restrict__ w_mu) {
    const int tid    = blockIdx.x * blockDim.x + threadIdx.x;
    const int stride = gridDim.x * blockDim.x;
    const int N4 = NW / 4;

    const float4* ws4 = (const float4*)w_sigma;
    const float4* wm4 = (const float4*)w_mu;
    float4* sp4 = (float4*)g_sp;

    float s_log = 0.f, s_sp = 0.f, s_abs = 0.f;
    for (int i = tid; i < N4; i += stride) {
        float4 x = ws4[i];
        float4 m = wm4[i];
        float4 sp;
        sp.x = softplusf(x.x); sp.y = softplusf(x.y);
        sp.z = softplusf(x.z); sp.w = softplusf(x.w);
        sp4[i] = sp;
        s_log += logf(sp.x) + logf(sp.y) + logf(sp.z) + logf(sp.w);
        s_sp  += sp.x + sp.y + sp.z + sp.w;
        s_abs += fabsf(m.x) + fabsf(m.y) + fabsf(m.z) + fabsf(m.w);
    }

    __shared__ float red0[256], red1[256], red2[256];
    red0[threadIdx.x] = s_log;
    red1[threadIdx.x] = s_sp;
    red2[threadIdx.x] = s_abs;
    __syncthreads();
    for (int off = 128; off > 0; off >>= 1) {
        if (threadIdx.x < off) {
            red0[threadIdx.x] += red0[threadIdx.x + off];
            red1[threadIdx.x] += red1[threadIdx.x + off];
            red2[threadIdx.x] += red2[threadIdx.x + off];
        }
        __syncthreads();
    }
    if (threadIdx.x == 0) {
        atomicAdd(&g_sums[0], (double)red0[0]);
        atomicAdd(&g_sums[1], (double)red1[0]);
        atomicAdd(&g_sums[2], (double)red2[0]);
    }
}

__global__ void finalize_kl(float* __restrict__ out) {
    double mean_log = g_sums[0] / (double)NW;
    double mean_sp  = g_sums[1] / (double)NW;
    double kl = -0.5 * ((double)SIZE_IN * mean_log - g_sums[2]
                        - (double)SIZE_IN * mean_sp);
    out[(size_t)2 * BATCH * SIZE_OUT] = (float)kl;
}

// -------------------- Fused dual GEMM --------------------
// mu_out    = A @ W_mu            + b_mu
// Sigma_out = (A*A) @ sp(W_sigma) + sp(b_sigma)
// Tile: BM=128, BN=64, BK=16; 256 threads; thread tile 8x4 per output path.
#define BM 128
#define BN 64
#define BK 16
#define TM 8
#define TN 4

__global__ __launch_bounds__(256, 2)
void fused_dual_gemm(const float* __restrict__ A,
                     const float* __restrict__ W1,
                     const float* __restrict__ b_mu,
                     const float* __restrict__ b_sigma,
                     float* __restrict__ out) {
    __shared__ float As[BK][BM];    // transposed A tile
    __shared__ float W1s[BK][BN];
    __shared__ float W2s[BK][BN];

    const float* __restrict__ W2 = g_sp;

    const int m0 = blockIdx.y * BM;
    const int n0 = blockIdx.x * BN;
    const int tid = threadIdx.x;
    const int tx = tid & 15;        // n direction
    const int ty = tid >> 4;        // m direction
    const int tm0 = ty * TM;
    const int tn0 = tx * TN;

    float acc1[TM][TN];
    float acc2[TM][TN];
#pragma unroll
    for (int m = 0; m < TM; m++)
#pragma unroll
        for (int n = 0; n < TN; n++) { acc1[m][n] = 0.f; acc2[m][n] = 0.f; }

    // W-tile load mapping: tid -> (k = tid>>4, n4 = tid&15)
    const int wk  = tid >> 4;
    const int wn4 = (tid & 15) * 4;

    for (int k0 = 0; k0 < SIZE_IN; k0 += BK) {
        // Load A tile (128 x 16) as 512 float4s, 2 per thread, store transposed.
#pragma unroll
        for (int l = 0; l < 2; l++) {
            int f  = tid + l * 256;
            int r  = f >> 2;
            int c4 = (f & 3) * 4;
            float4 v = *(const float4*)(A + (size_t)(m0 + r) * SIZE_IN + k0 + c4);
            As[c4 + 0][r] = v.x;
            As[c4 + 1][r] = v.y;
            As[c4 + 2][r] = v.z;
            As[c4 + 3][r] = v.w;
        }
        // Load W tiles (16 x 64), one float4 per thread per tile.
        {
            size_t goff = (size_t)(k0 + wk) * SIZE_OUT + n0 + wn4;
            *(float4*)&W1s[wk][wn4] = *(const float4*)(W1 + goff);
            *(float4*)&W2s[wk][wn4] = *(const float4*)(W2 + goff);
        }
        __syncthreads();

#pragma unroll
        for (int kk = 0; kk < BK; kk++) {
            float4 a0 = *(float4*)&As[kk][tm0];
            float4 a1 = *(float4*)&As[kk][tm0 + 4];
            float4 v1 = *(float4*)&W1s[kk][tn0];
            float4 v2 = *(float4*)&W2s[kk][tn0];
            float a[TM] = {a0.x, a0.y, a0.z, a0.w, a1.x, a1.y, a1.z, a1.w};
            float w1[TN] = {v1.x, v1.y, v1.z, v1.w};
            float w2[TN] = {v2.x, v2.y, v2.z, v2.w};
#pragma unroll
            for (int m = 0; m < TM; m++) {
                float am  = a[m];
                float am2 = am * am;
#pragma unroll
                for (int n = 0; n < TN; n++) {
                    acc1[m][n] = fmaf(am,  w1[n], acc1[m][n]);
                    acc2[m][n] = fmaf(am2, w2[n], acc2[m][n]);
                }
            }
        }
        __syncthreads();
    }

    // Epilogue: add biases, write both outputs with float4 stores.
    float b1[TN], b2[TN];
#pragma unroll
    for (int n = 0; n < TN; n++) {
        b1[n] = b_mu[n0 + tn0 + n];
        b2[n] = softplusf(b_sigma[n0 + tn0 + n]);
    }
    float* __restrict__ o1 = out;
    float* __restrict__ o2 = out + (size_t)BATCH * SIZE_OUT;
#pragma unroll
    for (int m = 0; m < TM; m++) {
        size_t row = (size_t)(m0 + tm0 + m);
        size_t off = row * SIZE_OUT + n0 + tn0;
        float4 r1, r2;
        r1.x = acc1[m][0] + b1[0]; r1.y = acc1[m][1] + b1[1];
        r1.z = acc1[m][2] + b1[2]; r1.w = acc1[m][3] + b1[3];
        r2.x = acc2[m][0] + b2[0]; r2.y = acc2[m][1] + b2[1];
        r2.z = acc2[m][2] + b2[2]; r2.w = acc2[m][3] + b2[3];
        *(float4*)(o1 + off) = r1;
        *(float4*)(o2 + off) = r2;
    }
}

extern "C" void kernel_launch(void* const* d_in, const int* in_sizes, int n_in,
                              void* d_out, int out_size) {
    const float* mu_in   = (const float*)d_in[0];
    // d_in[1] = sigma_in : unused by the reference outputs
    const float* w_mu    = (const float*)d_in[2];
    const float* w_sigma = (const float*)d_in[3];
    const float* b_mu    = (const float*)d_in[4];
    const float* b_sigma = (const float*)d_in[5];
    float* out = (float*)d_out;

    init_kernel<<<1, 32>>>();
    prep_kernel<<<1024, 256>>>(w_sigma, w_mu);

    dim3 grid(SIZE_OUT / BN, BATCH / BM);   // (64, 32)
    fused_dual_gemm<<<grid, 256>>>(mu_in, w_mu, b_mu, b_sigma, out);

    finalize_kl<<<1, 1>>>(out);
}

// round 3
// speedup vs baseline: 3.2226x; 3.2226x over previous
#include <cuda_runtime.h>
#include <math.h>
#include <stdint.h>

#define SZ 4096
#define NW (SZ*SZ)

// ---------------- scratch (static __device__, no runtime alloc) -------------
__device__ float  g_a[NW];     // tf32-rounded mu_in         [B][K]
__device__ float  g_w1t[NW];   // tf32-rounded w_mu^T        [N][K]
__device__ float  g_w2t[NW];   // tf32-rounded sp(w_sigma)^T [N][K]
__device__ double g_sums[3];   // [0]=sum log(sp) [1]=sum sp [2]=sum |w_mu|

__device__ __forceinline__ float softplusf(float x) {
    return x > 20.0f ? x : log1pf(expf(x));
}
__device__ __forceinline__ float tf32_rn(float x) {
    float y; asm("cvt.rna.tf32.f32 %0, %1;" : "=f"(y) : "f"(x)); return y;
}

// ---------------- prep kernels ----------------------------------------------
__global__ void init_kernel() {
    if (threadIdx.x < 3) g_sums[threadIdx.x] = 0.0;
}

// transpose + softplus + tf32 rounding + KL reduction
__global__ void prep_w(const float* __restrict__ w_mu,
                       const float* __restrict__ w_sigma) {
    __shared__ float t1[32][33];
    __shared__ float t2[32][33];
    __shared__ float red[3][256];
    const int bx = blockIdx.x * 32;   // n
    const int by = blockIdx.y * 32;   // k
    const int tx = threadIdx.x, ty = threadIdx.y;
    const int tid = ty * 32 + tx;

    float s_log = 0.f, s_sp = 0.f, s_abs = 0.f;
#pragma unroll
    for (int i = 0; i < 4; i++) {
        int k = by + ty + i * 8;
        int n = bx + tx;
        float wm = w_mu[(size_t)k * SZ + n];
        float ws = w_sigma[(size_t)k * SZ + n];
        float sp = softplusf(ws);
        s_log += logf(sp);
        s_sp  += sp;
        s_abs += fabsf(wm);
        t1[ty + i * 8][tx] = tf32_rn(wm);
        t2[ty + i * 8][tx] = tf32_rn(sp);
    }
    __syncthreads();
#pragma unroll
    for (int i = 0; i < 4; i++) {
        int n = bx + ty + i * 8;
        int k = by + tx;
        g_w1t[(size_t)n * SZ + k] = t1[tx][ty + i * 8];
        g_w2t[(size_t)n * SZ + k] = t2[tx][ty + i * 8];
    }

    red[0][tid] = s_log; red[1][tid] = s_sp; red[2][tid] = s_abs;
    __syncthreads();
    for (int off = 128; off > 0; off >>= 1) {
        if (tid < off) {
            red[0][tid] += red[0][tid + off];
            red[1][tid] += red[1][tid + off];
            red[2][tid] += red[2][tid + off];
        }
        __syncthreads();
    }
    if (tid == 0) {
        atomicAdd(&g_sums[0], (double)red[0][0]);
        atomicAdd(&g_sums[1], (double)red[1][0]);
        atomicAdd(&g_sums[2], (double)red[2][0]);
    }
}

__global__ void prep_a(const float* __restrict__ mu) {
    const float4* m4 = (const float4*)mu;
    float4* a4 = (float4*)g_a;
    int stride = gridDim.x * blockDim.x;
    for (int i = blockIdx.x * blockDim.x + threadIdx.x; i < NW / 4; i += stride) {
        float4 x = m4[i];
        float4 a;
        a.x = tf32_rn(x.x); a.y = tf32_rn(x.y);
        a.z = tf32_rn(x.z); a.w = tf32_rn(x.w);
        a4[i] = a;
    }
}

__global__ void finalize_kl(float* __restrict__ out) {
    double mean_log = g_sums[0] / (double)NW;
    double mean_sp  = g_sums[1] / (double)NW;
    double kl = -0.5 * ((double)SZ * mean_log - g_sums[2] - (double)SZ * mean_sp);
    out[(size_t)2 * SZ * SZ] = (float)kl;
}

// ---------------- main dual GEMM on mma.sync tf32 ----------------------------
// Per CTA: M=128 x N=128, both paths. 8 warps (2 m x 4 n), warp tile 64x32.
// mu_out    = A @ W1t^T + b_mu
// Sigma_out = (A.^2) @ W2t^T + sp(b_sigma)   (A^2 built in-register)
#define BM 128
#define BN 128
#define BK 32
#define STAGES 3
#define NCHUNK (SZ / BK)       // 128
#define PITCH 36               // floats per smem row (conflict-free)

#define TILE_BYTES (128 * PITCH * 4)       // 18432 per operand tile
#define STAGE_BYTES (3 * TILE_BYTES)       // A, W1, W2
#define SMEM_TOTAL (STAGES * STAGE_BYTES)  // 165888

__device__ __forceinline__ void cp16(uint32_t dst, const float* src) {
    asm volatile("cp.async.cg.shared.global [%0], [%1], 16;"
                 :: "r"(dst), "l"(__cvta_generic_to_global(src)));
}
__device__ __forceinline__ uint32_t smem_u32(const void* p) {
    uint32_t a;
    asm("{ .reg .u64 t; cvta.to.shared.u64 t, %1; cvt.u32.u64 %0, t; }"
        : "=r"(a) : "l"(p));
    return a;
}

#define MMA_TF32(d, a0, a1, a2, a3, b0, b1) \
    asm volatile( \
        "mma.sync.aligned.m16n8k8.row.col.f32.tf32.tf32.f32 " \
        "{%0,%1,%2,%3}, {%4,%5,%6,%7}, {%8,%9}, {%0,%1,%2,%3};" \
        : "+f"((d)[0]), "+f"((d)[1]), "+f"((d)[2]), "+f"((d)[3]) \
        : "r"(__float_as_uint(a0)), "r"(__float_as_uint(a1)), \
          "r"(__float_as_uint(a2)), "r"(__float_as_uint(a3)), \
          "r"(__float_as_uint(b0)), "r"(__float_as_uint(b1)))

__global__ __launch_bounds__(256, 1)
void gemm_tf32(const float* __restrict__ b_mu,
               const float* __restrict__ b_sigma,
               float* __restrict__ out) {
    extern __shared__ char smem[];
    const uint32_t sb = smem_u32(smem);

    const int tid = threadIdx.x;
    const int wid = tid >> 5;
    const int lid = tid & 31;
    const int lr  = lid >> 2;     // 0..7
    const int lc  = lid & 3;      // 0..3
    const int wm  = wid & 1;      // m-block (64 rows)
    const int wn  = wid >> 1;     // n-block (32 cols)
    const int m0 = blockIdx.y * BM;
    const int n0 = blockIdx.x * BN;

    float acc1[4][4][4];   // [mt][nt][4]
    float acc2[4][4][4];
#pragma unroll
    for (int mt = 0; mt < 4; mt++)
#pragma unroll
        for (int nt = 0; nt < 4; nt++)
#pragma unroll
            for (int q = 0; q < 4; q++) { acc1[mt][nt][q] = 0.f; acc2[mt][nt][q] = 0.f; }

    // Stage loader: 12 x 16B cp.async per thread (A, W1, W2: 128x32 floats each)
    auto load_stage = [&](int chunk, int s) {
        const int k0 = chunk * BK;
        const uint32_t base = sb + s * STAGE_BYTES;
#pragma unroll
        for (int i = 0; i < 4; i++) {
            int f = tid + i * 256;         // 0..1023
            int r = f >> 3, c4 = f & 7;
            uint32_t doff = (uint32_t)(r * (PITCH * 4) + c4 * 16);
            size_t goff = (size_t)(m0 + r) * SZ + k0 + c4 * 4;
            cp16(base + doff, g_a + goff);
            size_t woff = (size_t)(n0 + r) * SZ + k0 + c4 * 4;
            cp16(base + TILE_BYTES + doff,     g_w1t + woff);
            cp16(base + 2 * TILE_BYTES + doff, g_w2t + woff);
        }
        asm volatile("cp.async.commit_group;" ::: "memory");
    };

    // Prologue: prefetch STAGES-1 chunks
    load_stage(0, 0);
    load_stage(1, 1);

    for (int c = 0; c < NCHUNK; c++) {
        const int s = c % STAGES;
        asm volatile("cp.async.wait_group %0;" :: "n"(STAGES - 2) : "memory");
        __syncthreads();

        // prefetch chunk c+STAGES-1 into the stage freed at iteration c-1
        if (c + STAGES - 1 < NCHUNK)
            load_stage(c + STAGES - 1, (c + STAGES - 1) % STAGES);

        const float* As  = (const float*)(smem + s * STAGE_BYTES);
        const float* W1s = (const float*)(smem + s * STAGE_BYTES + TILE_BYTES);
        const float* W2s = (const float*)(smem + s * STAGE_BYTES + 2 * TILE_BYTES);

#pragma unroll
        for (int ks = 0; ks < BK / 8; ks++) {
            const int k0 = ks * 8;
            float a[4][4], a2[4][4];
#pragma unroll
            for (int mt = 0; mt < 4; mt++) {
                const float* p = As + (wm * 64 + mt * 16 + lr) * PITCH + k0 + lc;
                a[mt][0] = p[0];
                a[mt][1] = p[8 * PITCH];
                a[mt][2] = p[4];
                a[mt][3] = p[8 * PITCH + 4];
#pragma unroll
                for (int q = 0; q < 4; q++)
                    a2[mt][q] = tf32_rn(a[mt][q] * a[mt][q]);
            }
#pragma unroll
            for (int nt = 0; nt < 4; nt++) {
                const float* p1 = W1s + (wn * 32 + nt * 8 + lr) * PITCH + k0 + lc;
                float b0 = p1[0], b1 = p1[4];
#pragma unroll
                for (int mt = 0; mt < 4; mt++)
                    MMA_TF32(acc1[mt][nt], a[mt][0], a[mt][1], a[mt][2], a[mt][3], b0, b1);
                const float* p2 = W2s + (wn * 32 + nt * 8 + lr) * PITCH + k0 + lc;
                float c0 = p2[0], c1 = p2[4];
#pragma unroll
                for (int mt = 0; mt < 4; mt++)
                    MMA_TF32(acc2[mt][nt], a2[mt][0], a2[mt][1], a2[mt][2], a2[mt][3], c0, c1);
            }
        }
        __syncthreads();
    }

    // ---------------- epilogue ----------------
    float* o1 = out;
    float* o2 = out + (size_t)SZ * SZ;
#pragma unroll
    for (int nt = 0; nt < 4; nt++) {
        int col = n0 + wn * 32 + nt * 8 + lc * 2;
        float bm0 = b_mu[col],  bm1 = b_mu[col + 1];
        float bs0 = softplusf(b_sigma[col]), bs1 = softplusf(b_sigma[col + 1]);
#pragma unroll
        for (int mt = 0; mt < 4; mt++) {
            int row = m0 + wm * 64 + mt * 16 + lr;
            float2 v;
            v.x = acc1[mt][nt][0] + bm0; v.y = acc1[mt][nt][1] + bm1;
            *(float2*)(o1 + (size_t)row * SZ + col) = v;
            v.x = acc1[mt][nt][2] + bm0; v.y = acc1[mt][nt][3] + bm1;
            *(float2*)(o1 + (size_t)(row + 8) * SZ + col) = v;
            v.x = acc2[mt][nt][0] + bs0; v.y = acc2[mt][nt][1] + bs1;
            *(float2*)(o2 + (size_t)row * SZ + col) = v;
            v.x = acc2[mt][nt][2] + bs0; v.y = acc2[mt][nt][3] + bs1;
            *(float2*)(o2 + (size_t)(row + 8) * SZ + col) = v;
        }
    }
}

// ---------------- launch -----------------------------------------------------
extern "C" void kernel_launch(void* const* d_in, const int* in_sizes, int n_in,
                              void* d_out, int out_size) {
    const float* mu_in   = (const float*)d_in[0];
    // d_in[1] = sigma_in : unused by the reference outputs
    const float* w_mu    = (const float*)d_in[2];
    const float* w_sigma = (const float*)d_in[3];
    const float* b_mu    = (const float*)d_in[4];
    const float* b_sigma = (const float*)d_in[5];
    float* out = (float*)d_out;

    cudaFuncSetAttribute(gemm_tf32, cudaFuncAttributeMaxDynamicSharedMemorySize,
                         SMEM_TOTAL);

    init_kernel<<<1, 32>>>();
    prep_w<<<dim3(128, 128), dim3(32, 8)>>>(w_mu, w_sigma);
    prep_a<<<4096, 256>>>(mu_in);
    gemm_tf32<<<dim3(SZ / BN, SZ / BM), 256, SMEM_TOTAL>>>(b_mu, b_sigma, out);
    finalize_kl<<<1, 1>>>(out);
}